// round 12
// baseline (speedup 1.0000x reference)
#include <cuda_runtime.h>
#include <cstdint>

// LZC48 over binary float spikes.
// Input:  [n_words, 48] float32, values exactly 0.0f or 1.0f, MSB first.
// Output: [n_words, 6]  float32, 6-bit MSB-first encoding of leading-zero count
//         (48 -> 110000 for an all-zero word).
//
// Champion structure (stable across R1/R8/R9/R10/R11: 47.6-48.8us kernel,
// rel_err 0, DRAM 76-80% of spec) + R12 delta: streaming stores (__stcs) on
// the output path so write-stream lines evict early and writebacks don't
// linger against the read stream. Model, verified over 6 measured kernels:
//   * DRAM fetch is 128B line-granular (LDG and TMA identical; TMA
//     L2_PROMOTION_NONE has no effect). At 192B word stride each word's 32B
//     prefix requests exactly one distinct line -> 268MB read floor + 50MB
//     write; measured 306MB.
//   * Achieved BW for this fetch-2-skip-1 line pattern is ~6.3TB/s across all
//     structural variants (occupancy/MLP/pipelining invariant) -> ~48us wall.
//   * Paired-lane loads (lanes 2i,2i+1 take the two 16B halves of word i's
//     prefix) give 1 L1 wavefront per word.
//   * Fallback (prefix all zero, P=1/256) scans floats 8..47; mostly L2 hits
//     on already-fetched lines, ~0.2% extra traffic. Loads stay default
//     policy (R2 measured __ldcg-everything as slightly worse).

constexpr int TPB = 256;   // threads per block
constexpr int WPB = 256;   // words per block

__global__ __launch_bounds__(TPB)
void lzc48_kernel(const uint4* __restrict__ in4,   // word w at in4[w*12 .. w*12+11]
                  float* __restrict__ out,         // [n_words*6]
                  int n_words)
{
    // even halves at sbuf[0..255], odd halves at sbuf[260..515].
    // The 260 offset (byte 4160, == 64 mod 128) makes the interleaved
    // even/odd STS.128 pattern conflict-free in every 8-lane phase.
    __shared__ uint4 sbuf[520];
    __shared__ float sout[WPB * 6];

    const int tile  = blockIdx.x * WPB;
    int count = n_words - tile;
    if (count > WPB) count = WPB;

    // ---- Load sector 0 (first 8 floats = 32B) of each word in the tile ----
    // j = 2*word + half. Lanes (2i, 2i+1) load the two 16B halves of word i's
    // prefix; both fall in the same 128B line -> 1 wavefront per word.
    #pragma unroll
    for (int k = 0; k < 2; k++) {
        int j = k * TPB + threadIdx.x;          // 0 .. 511
        int w = j >> 1;
        int h = j & 1;
        if (w < count) {
            uint4 v = in4[(size_t)(tile + w) * 12 + h];
            sbuf[(h ? 260 : 0) + w] = v;
        }
    }
    __syncthreads();

    const int t = threadIdx.x;
    if (t < count) {
        uint4 e = sbuf[t];         // floats 0..3 of the word (MSB side)
        uint4 o = sbuf[260 + t];   // floats 4..7

        // 8-bit mask, bit7 = float0 (MSB first). Inputs are exactly 0.0f/1.0f,
        // so a nonzero bit pattern <=> value 1.0f.
        unsigned m = (e.x ? 128u : 0u) | (e.y ? 64u : 0u) | (e.z ? 32u : 0u) | (e.w ? 16u : 0u)
                   | (o.x ?   8u : 0u) | (o.y ?  4u : 0u) | (o.z ?  2u : 0u) | (o.w ?  1u : 0u);

        int lzc;
        if (m) {
            lzc = __clz(m << 24);              // 0..7
        } else {
            // Rare fallback (P = 1/256): scan remaining 40 floats.
            const uint4* wp = in4 + (size_t)(tile + t) * 12;
            unsigned long long acc = 0ull;
            #pragma unroll
            for (int i = 2; i < 12; i++) {
                uint4 v = wp[i];
                unsigned nib = (v.x ? 8u : 0u) | (v.y ? 4u : 0u)
                             | (v.z ? 2u : 0u) | (v.w ? 1u : 0u);
                acc = (acc << 4) | nib;        // 40 bits; bit39 = float 8
            }
            lzc = acc ? (8 + __clzll(acc << 24)) : 48;
        }

        // 6-bit MSB-first encoding into smem staging (stride 6 floats:
        // STS.64x3 is conflict-free: 6t mod 32 distinct over each 16-lane phase).
        float* so = sout + t * 6;
        so[0] = (float)((lzc >> 5) & 1);
        so[1] = (float)((lzc >> 4) & 1);
        so[2] = (float)((lzc >> 3) & 1);
        so[3] = (float)((lzc >> 2) & 1);
        so[4] = (float)((lzc >> 1) & 1);
        so[5] = (float)( lzc       & 1);
    }
    __syncthreads();

    // ---- Coalesced streaming write of the tile's 256*6 floats = 384 float4 ----
    if (count == WPB) {
        float4* ob = reinterpret_cast<float4*>(out + (size_t)tile * 6);
        const float4* sb = reinterpret_cast<const float4*>(sout);
        __stcs(ob + t, sb[t]);
        if (t < (WPB * 6 / 4) - TPB)           // remaining 128 float4
            __stcs(ob + TPB + t, sb[TPB + t]);
    } else {
        // Partial last tile: scalar writes, no overrun into the next tile.
        for (int j = t; j < count * 6; j += TPB)
            __stcs(out + (size_t)tile * 6 + j, sout[j]);
    }
}

extern "C" void kernel_launch(void* const* d_in, const int* in_sizes, int n_in,
                              void* d_out, int out_size)
{
    const uint4* in4 = (const uint4*)d_in[0];
    float* out = (float*)d_out;
    const int n_words = in_sizes[0] / 48;       // 1024*2048 = 2,097,152
    const int grid = (n_words + WPB - 1) / WPB; // 8192
    lzc48_kernel<<<grid, TPB>>>(in4, out, n_words);
}